// round 1
// baseline (speedup 1.0000x reference)
#include <cuda_runtime.h>

// predictor_interp2d: nearest-bot gather onto a 256x256 grid.
// Inputs (metadata order):
//   d_in[0] = R_pc  [B=2, C=4, N=1024] float32
//   d_in[1] = XY_pc [B=2, 2,   N=1024] float32  (x plane then y plane)
// Output: R_grd [B, C, 256, 256] float32
//
// Per grid cell g (gx=(j+0.5)/256, gy=(i+0.5)/256, exact in fp32):
//   d2(n) = (x_n^2 + y_n^2) - 2*(gx*x_n + gy*y_n)   (||g||^2 omitted, matches ref)
//   idx   = argmin_n d2(n)   (first min on ties)
//   out[b,c,g] = R_pc[b,c,idx]
//
// Rounding is matched to the JAX reference op-by-op:
//   pn2 = rn(x*x) + rn(y*y)           (elementwise mul, 2-elem reduce)
//   dot = fmaf(gy, y, rn(gx*x))       (dot_general K=2 accumulation, d=0 first)
//   d2  = fmaf(-2, dot, pn2)          (-2*dot exact; single rounding)

#define GH 256
#define GW 256
#define NPTS 1024
#define NBATCH 2
#define NCH 4
#define TPB 128   // threads per block; 1 cell per thread
#define NBLK ((NBATCH * GH * GW) / TPB)   // 1024 blocks

__global__ void __launch_bounds__(TPB)
nn_gather_kernel(const float* __restrict__ R,
                 const float* __restrict__ XY,
                 float* __restrict__ out)
{
    __shared__ float4 pts[NPTS];   // (x, y, x^2+y^2, unused) : 16 KB

    const int tid  = threadIdx.x;
    const int cell = blockIdx.x * TPB + tid;     // [0, 131072)
    const int b    = cell >> 16;                 // batch
    const int g    = cell & 0xFFFF;              // grid cell within batch

    // ---- stage point data into shared memory (coalesced) ----
    const float* xp = XY + b * (2 * NPTS);
    const float* yp = xp + NPTS;
#pragma unroll
    for (int i = 0; i < NPTS / TPB; ++i) {
        const int n = tid + i * TPB;
        const float x = xp[n];
        const float y = yp[n];
        const float pn2 = __fadd_rn(__fmul_rn(x, x), __fmul_rn(y, y));
        pts[n] = make_float4(x, y, pn2, 0.0f);
    }
    __syncthreads();

    // ---- grid-cell coordinates (exact fp32: (2k+1)/512) ----
    const float gx = ((float)(g & (GW - 1)) + 0.5f) * (1.0f / GW);
    const float gy = ((float)(g >> 8)       + 0.5f) * (1.0f / GH);

    // ---- brute-force argmin over all points ----
    float best = 3.4e38f;
    int   bidx = 0;
#pragma unroll 8
    for (int n = 0; n < NPTS; ++n) {
        const float4 q  = pts[n];
        const float dot = __fmaf_rn(gy, q.y, __fmul_rn(gx, q.x));
        const float d2  = __fmaf_rn(-2.0f, dot, q.z);
        if (d2 < best) { best = d2; bidx = n; }   // strict < keeps first min
    }

    // ---- gather C=4 channels, coalesced store per channel plane ----
    const float* Rb = R + b * (NCH * NPTS);
#pragma unroll
    for (int c = 0; c < NCH; ++c) {
        out[(b * NCH + c) * (GH * GW) + g] = __ldg(Rb + c * NPTS + bidx);
    }
}

extern "C" void kernel_launch(void* const* d_in, const int* in_sizes, int n_in,
                              void* d_out, int out_size)
{
    const float* R  = (const float*)d_in[0];
    const float* XY = (const float*)d_in[1];
    float* out = (float*)d_out;
    nn_gather_kernel<<<NBLK, TPB>>>(R, XY, out);
}

// round 2
// speedup vs baseline: 5.8892x; 5.8892x over previous
#include <cuda_runtime.h>
#include <math.h>

// predictor_interp2d: nearest-bot gather onto a 256x256 grid, Voronoi-pruned.
//
// Inputs: d_in[0] = R_pc [B=2,C=4,N=1024] f32 ; d_in[1] = XY_pc [B=2,2,N=1024] f32
// Output: R_grd [B,C,256,256] f32
//
// Exact-match strategy: per-cell argmin uses the reference-rounded formula
//   pn2 = rn(x*x)+rn(y*y); dot = fmaf(gy,y,rn(gx*x)); d2 = fmaf(-2,dot,pn2)
// over a candidate subset scanned in ascending point order with strict '<'.
// Candidate pruning (per 8x8-cell tile): p kept iff
//   dist(tile_center,p) <= min_q dist(tile_center,q) + 2*R_tile + 1e-3
// which guarantees every possible argmin (incl. fp-noise winners and exact
// ties) is in the set; pruned points are strictly farther by >> fp error.

#define GH 256
#define GW 256
#define NPTS 1024
#define NCH 4
#define TILE 8                 // 8x8 cells per block
#define TPB 64                 // 1 thread per cell
#define TILES_X (GW / TILE)    // 32
#define TILES_PER_B (TILES_X * (GH / TILE))   // 1024
#define CAP 512                // candidate list capacity
#define PTS_PER_T (NPTS / TPB) // 16 points owned per thread (contiguous)

__device__ __forceinline__ int pad(int n) { return n + (n >> 4); } // bank-safe

__global__ void __launch_bounds__(TPB)
nn_voronoi_kernel(const float* __restrict__ R,
                  const float* __restrict__ XY,
                  float* __restrict__ out)
{
    __shared__ float sx[NPTS + NPTS / 16];   // padded x coords
    __shared__ float sy[NPTS + NPTS / 16];   // padded y coords
    __shared__ float4 cand[CAP];             // (x, y, pn2, idx-as-float), n-ascending
    __shared__ float s_red[2];
    __shared__ int   s_wtot[2];

    const int tid  = threadIdx.x;
    const int lane = tid & 31;
    const int warp = tid >> 5;

    const int b    = blockIdx.x >> 10;        // batch
    const int tile = blockIdx.x & 1023;
    const int r0   = (tile >> 5) * TILE;      // tile origin (cell coords)
    const int c0   = (tile & 31) * TILE;

    // ---- stage point coords into padded shared memory ----
    const float* xp = XY + b * (2 * NPTS);
    const float* yp = xp + NPTS;
#pragma unroll
    for (int k = 0; k < NPTS / TPB; ++k) {
        const int n = tid + k * TPB;
        sx[pad(n)] = xp[n];
        sy[pad(n)] = yp[n];
    }
    __syncthreads();

    // ---- phase A1: min true squared distance to tile center ----
    const float gcx = ((float)c0 + 4.0f) * (1.0f / GW);
    const float gcy = ((float)r0 + 4.0f) * (1.0f / GH);
    const int   pbase = 17 * tid;            // pad(16*tid) ; contiguous run

    float m = 3.4e38f;
#pragma unroll
    for (int i = 0; i < PTS_PER_T; ++i) {
        const float dx = gcx - sx[pbase + i];
        const float dy = gcy - sy[pbase + i];
        m = fminf(m, __fmaf_rn(dy, dy, dx * dx));
    }
#pragma unroll
    for (int o = 16; o > 0; o >>= 1)
        m = fminf(m, __shfl_xor_sync(0xffffffffu, m, o));
    if (lane == 0) s_red[warp] = m;
    __syncthreads();
    const float d2min = fminf(s_red[0], s_red[1]);

    // prune radius: dmin + 2*R_tile + margin   (R_tile = 3.5*sqrt(2)/256)
    const float T = sqrtf(d2min) + 2.0f * 0.0193434f + 1.0e-3f;
    const float thresh2 = T * T;

    // ---- phase A2: flag + ordered compaction of candidates ----
    unsigned fl = 0;
#pragma unroll
    for (int i = 0; i < PTS_PER_T; ++i) {
        const float dx = gcx - sx[pbase + i];
        const float dy = gcy - sy[pbase + i];
        const float d2 = __fmaf_rn(dy, dy, dx * dx);
        fl |= (d2 <= thresh2) ? (1u << i) : 0u;
    }
    const int cnt = __popc(fl);
    int inc = cnt;
#pragma unroll
    for (int o = 1; o < 32; o <<= 1) {
        const int v = __shfl_up_sync(0xffffffffu, inc, o);
        if (lane >= o) inc += v;
    }
    if (lane == 31) s_wtot[warp] = inc;
    __syncthreads();
    const int w0 = s_wtot[0];
    const int total = w0 + s_wtot[1];
    int pos = inc - cnt + (warp ? w0 : 0);

    const bool overflow = (total > CAP);
    if (!overflow && cnt) {
        const int nbase = PTS_PER_T * tid;
#pragma unroll
        for (int i = 0; i < PTS_PER_T; ++i) {
            if ((fl >> i) & 1u) {
                const float x = sx[pbase + i];
                const float y = sy[pbase + i];
                const float pn2 = __fadd_rn(__fmul_rn(x, x), __fmul_rn(y, y));
                cand[pos++] = make_float4(x, y, pn2, __int_as_float(nbase + i));
            }
        }
    }
    __syncthreads();

    // ---- phase B: exact argmin over candidates (reference rounding) ----
    const int r = r0 + (tid >> 3);
    const int c = c0 + (tid & 7);
    const float gx = ((float)c + 0.5f) * (1.0f / GW);
    const float gy = ((float)r + 0.5f) * (1.0f / GH);

    float best = 3.4e38f;
    int   bn   = 0;
    if (!overflow) {
        for (int i = 0; i < total; ++i) {
            const float4 q = cand[i];
            const float dot = __fmaf_rn(gy, q.y, __fmul_rn(gx, q.x));
            const float d2  = __fmaf_rn(-2.0f, dot, q.z);
            if (d2 < best) { best = d2; bn = __float_as_int(q.w); }
        }
    } else {
        for (int n = 0; n < NPTS; ++n) {           // safe fallback (broadcast)
            const float x = sx[pad(n)];
            const float y = sy[pad(n)];
            const float pn2 = __fadd_rn(__fmul_rn(x, x), __fmul_rn(y, y));
            const float dot = __fmaf_rn(gy, y, __fmul_rn(gx, x));
            const float d2  = __fmaf_rn(-2.0f, dot, pn2);
            if (d2 < best) { best = d2; bn = n; }
        }
    }

    // ---- gather channels + store ----
    const float* Rb = R + b * (NCH * NPTS);
    const int g = r * GW + c;
#pragma unroll
    for (int ch = 0; ch < NCH; ++ch)
        out[(b * NCH + ch) * (GH * GW) + g] = __ldg(Rb + ch * NPTS + bn);
}

extern "C" void kernel_launch(void* const* d_in, const int* in_sizes, int n_in,
                              void* d_out, int out_size)
{
    const float* R  = (const float*)d_in[0];
    const float* XY = (const float*)d_in[1];
    nn_voronoi_kernel<<<2 * TILES_PER_B, TPB>>>(R, XY, (float*)d_out);
}

// round 3
// speedup vs baseline: 6.0299x; 1.0239x over previous
#include <cuda_runtime.h>
#include <math.h>

// predictor_interp2d: nearest-bot gather onto a 256x256 grid, Voronoi-pruned.
//
// Inputs: d_in[0] = R_pc [B=2,C=4,N=1024] f32 ; d_in[1] = XY_pc [B=2,2,N=1024] f32
// Output: R_grd [B,C,256,256] f32
//
// Per-cell argmin uses the reference-rounded formula
//   pn2 = rn(x*x)+rn(y*y); dot = fmaf(gy,y,rn(gx*x)); d2 = fmaf(-2,dot,pn2)
// over a candidate subset scanned in ascending point order with strict '<'
// (bit-exact value + tie-break vs the JAX reference).
// Pruning per 16x16-cell tile: keep p iff
//   dist(tile_center,p) <= min_q dist(tile_center,q) + 2*R_tile + 1e-3
// (R_tile = half-diagonal of the tile's cell-center span = 7.5*sqrt(2)/256).
// Any possible per-cell winner satisfies this bound with >1e-3 slack over fp
// noise, so pruned points can neither win nor tie. Overflow -> full scan.

#define GH 256
#define GW 256
#define NPTS 1024
#define NCH 4
#define TILE 16                 // 16x16 cells per block
#define TPB 256                 // 1 thread per cell
#define TILES_PER_B 256         // (256/16)^2
#define CAP 384                 // candidate capacity (expected ~33)
#define PPT 4                   // points owned per thread (1024/256)
#define RTILE 0.041434f         // 7.5*sqrt(2)/256 (rounded up)

__device__ __forceinline__ int pad(int n) { return n + (n >> 4); }

__global__ void __launch_bounds__(TPB)
nn_voronoi16_kernel(const float* __restrict__ R,
                    const float* __restrict__ XY,
                    float* __restrict__ out)
{
    __shared__ float sx[NPTS + NPTS / 16];
    __shared__ float sy[NPTS + NPTS / 16];
    __shared__ float4 cand[CAP];            // (x, y, pn2, idx), ascending n
    __shared__ float s_red[8];
    __shared__ int   s_wtot[8];

    const int tid  = threadIdx.x;
    const int lane = tid & 31;
    const int warp = tid >> 5;

    const int b    = blockIdx.x >> 8;       // batch
    const int tile = blockIdx.x & 255;
    const int r0   = (tile >> 4) * TILE;
    const int c0   = (tile & 15) * TILE;

    // ---- stage coords (coalesced, padded) ----
    const float* xp = XY + b * (2 * NPTS);
    const float* yp = xp + NPTS;
#pragma unroll
    for (int k = 0; k < NPTS / TPB; ++k) {
        const int n = tid + k * TPB;
        sx[pad(n)] = xp[n];
        sy[pad(n)] = yp[n];
    }
    __syncthreads();

    // ---- phase A (single pass): center distances, cached in registers ----
    const float gcx = ((float)c0 + 8.0f) * (1.0f / GW);   // tile-center coords
    const float gcy = ((float)r0 + 8.0f) * (1.0f / GH);
    const int pbase = 4 * tid + (tid >> 2);               // pad(4*tid), contiguous

    float d2r[PPT];
    float m = 3.4e38f;
#pragma unroll
    for (int i = 0; i < PPT; ++i) {
        const float dx = gcx - sx[pbase + i];
        const float dy = gcy - sy[pbase + i];
        d2r[i] = __fmaf_rn(dy, dy, dx * dx);
        m = fminf(m, d2r[i]);
    }
#pragma unroll
    for (int o = 16; o > 0; o >>= 1)
        m = fminf(m, __shfl_xor_sync(0xffffffffu, m, o));
    if (lane == 0) s_red[warp] = m;
    __syncthreads();
    float d2min = s_red[0];
#pragma unroll
    for (int w = 1; w < 8; ++w) d2min = fminf(d2min, s_red[w]);

    const float T = sqrtf(d2min) + 2.0f * RTILE + 1.0e-3f;
    const float thresh2 = T * T;

    // ---- flag (from registers) + ordered block compaction ----
    unsigned fl = 0;
#pragma unroll
    for (int i = 0; i < PPT; ++i)
        fl |= (d2r[i] <= thresh2) ? (1u << i) : 0u;

    const int cnt = __popc(fl);
    int inc = cnt;
#pragma unroll
    for (int o = 1; o < 32; o <<= 1) {
        const int v = __shfl_up_sync(0xffffffffu, inc, o);
        if (lane >= o) inc += v;
    }
    if (lane == 31) s_wtot[warp] = inc;
    __syncthreads();
    int wpre = 0, total = 0;
#pragma unroll
    for (int w = 0; w < 8; ++w) {
        const int v = s_wtot[w];
        wpre += (w < warp) ? v : 0;
        total += v;
    }
    int pos = wpre + inc - cnt;

    const bool overflow = (total > CAP);
    if (!overflow && cnt) {
        const int nbase = PPT * tid;
#pragma unroll
        for (int i = 0; i < PPT; ++i) {
            if ((fl >> i) & 1u) {
                const float x = sx[pbase + i];
                const float y = sy[pbase + i];
                const float pn2 = __fadd_rn(__fmul_rn(x, x), __fmul_rn(y, y));
                cand[pos++] = make_float4(x, y, pn2, __int_as_float(nbase + i));
            }
        }
    }
    __syncthreads();

    // ---- phase B: exact argmin over candidates (reference rounding) ----
    const int r = r0 + (tid >> 4);
    const int c = c0 + (tid & 15);
    const float gx = ((float)c + 0.5f) * (1.0f / GW);
    const float gy = ((float)r + 0.5f) * (1.0f / GH);

    float best = 3.4e38f;
    int   bn   = 0;
    if (!overflow) {
        for (int i = 0; i < total; ++i) {
            const float4 q = cand[i];                         // broadcast LDS.128
            const float dot = __fmaf_rn(gy, q.y, __fmul_rn(gx, q.x));
            const float d2  = __fmaf_rn(-2.0f, dot, q.z);
            if (d2 < best) { best = d2; bn = __float_as_int(q.w); }
        }
    } else {
        for (int n = 0; n < NPTS; ++n) {                      // safe fallback
            const float x = sx[pad(n)];
            const float y = sy[pad(n)];
            const float pn2 = __fadd_rn(__fmul_rn(x, x), __fmul_rn(y, y));
            const float dot = __fmaf_rn(gy, y, __fmul_rn(gx, x));
            const float d2  = __fmaf_rn(-2.0f, dot, pn2);
            if (d2 < best) { best = d2; bn = n; }
        }
    }

    // ---- gather channels + store ----
    const float* Rb = R + b * (NCH * NPTS);
    const int g = r * GW + c;
#pragma unroll
    for (int ch = 0; ch < NCH; ++ch)
        out[(b * NCH + ch) * (GH * GW) + g] = __ldg(Rb + ch * NPTS + bn);
}

extern "C" void kernel_launch(void* const* d_in, const int* in_sizes, int n_in,
                              void* d_out, int out_size)
{
    const float* R  = (const float*)d_in[0];
    const float* XY = (const float*)d_in[1];
    nn_voronoi16_kernel<<<2 * TILES_PER_B, TPB>>>(R, XY, (float*)d_out);
}

// round 5
// speedup vs baseline: 7.4539x; 1.2362x over previous
#include <cuda_runtime.h>
#include <math.h>

// predictor_interp2d: nearest-bot gather onto a 256x256 grid, Voronoi-pruned.
//
// Inputs: d_in[0] = R_pc [B=2,C=4,N=1024] f32 ; d_in[1] = XY_pc [B=2,2,N=1024] f32
// Output: R_grd [B,C,256,256] f32
//
// Per-cell argmin uses the reference-rounded formula
//   pn2 = rn(x*x)+rn(y*y); dot = fmaf(gy,y,rn(gx*x)); d2 = fmaf(-2,dot,pn2)
// over a candidate subset scanned in ascending point order, tie-break = first
// (smallest index), bit-exact vs the JAX reference.
// Pruning per 16x16-cell tile: keep p iff
//   dist(tile_center,p) <= min_q dist(tile_center,q) + 2*R_tile + 1e-3
// (R_tile = 7.5*sqrt(2)/256). Pruned points are farther by >> fp noise, so
// they can neither win nor tie. Overflow -> full scan from gmem (exact).

#define GH 256
#define GW 256
#define NPTS 1024
#define NCH 4
#define TILE 16
#define TPB 256
#define TILES_PER_B 256
#define CAP 384                 // capacity incl. sentinel slot
#define RTILE 0.041434f         // 7.5*sqrt(2)/256, rounded up

__global__ void __launch_bounds__(TPB, 6)
nn_voronoi_reg_kernel(const float* __restrict__ R,
                      const float* __restrict__ XY,
                      float* __restrict__ out)
{
    __shared__ float4 cand[CAP];     // (x, y, pn2, idx-as-int), ascending n
    __shared__ float s_red[8];
    __shared__ int   s_wtot[8];

    const int tid  = threadIdx.x;
    const int lane = tid & 31;
    const int warp = tid >> 5;

    const int b    = blockIdx.x >> 8;
    const int tile = blockIdx.x & 255;
    const int r0   = (tile >> 4) * TILE;
    const int c0   = (tile & 15) * TILE;

    const float* xp = XY + b * (2 * NPTS);
    const float* yp = xp + NPTS;

    // ---- phase A: own 4 points in registers (2x LDG.128, coalesced) ----
    const float4 xv = *(const float4*)(xp + 4 * tid);
    const float4 yv = *(const float4*)(yp + 4 * tid);
    const float px[4] = { xv.x, xv.y, xv.z, xv.w };
    const float py[4] = { yv.x, yv.y, yv.z, yv.w };

    const float gcx = ((float)c0 + 8.0f) * (1.0f / GW);
    const float gcy = ((float)r0 + 8.0f) * (1.0f / GH);

    float d2r[4];
    float m = 3.4e38f;
#pragma unroll
    for (int i = 0; i < 4; ++i) {
        const float dx = gcx - px[i];
        const float dy = gcy - py[i];
        d2r[i] = __fmaf_rn(dy, dy, dx * dx);
        m = fminf(m, d2r[i]);
    }
#pragma unroll
    for (int o = 16; o > 0; o >>= 1)
        m = fminf(m, __shfl_xor_sync(0xffffffffu, m, o));
    if (lane == 0) s_red[warp] = m;
    __syncthreads();
    float d2min = s_red[0];
#pragma unroll
    for (int w = 1; w < 8; ++w) d2min = fminf(d2min, s_red[w]);

    const float T = sqrtf(d2min) + 2.0f * RTILE + 1.0e-3f;
    const float thresh2 = T * T;

    // ---- flag + ordered block compaction ----
    unsigned fl = 0;
#pragma unroll
    for (int i = 0; i < 4; ++i)
        fl |= (d2r[i] <= thresh2) ? (1u << i) : 0u;

    const int cnt = __popc(fl);
    int inc = cnt;
#pragma unroll
    for (int o = 1; o < 32; o <<= 1) {
        const int v = __shfl_up_sync(0xffffffffu, inc, o);
        if (lane >= o) inc += v;
    }
    if (lane == 31) s_wtot[warp] = inc;
    __syncthreads();
    int wpre = 0, total = 0;
#pragma unroll
    for (int w = 0; w < 8; ++w) {
        const int v = s_wtot[w];
        wpre += (w < warp) ? v : 0;
        total += v;
    }
    int pos = wpre + inc - cnt;

    const bool overflow = (total > CAP - 1);   // keep one sentinel slot
    if (!overflow) {
        if (cnt) {
            const int nbase = 4 * tid;
#pragma unroll
            for (int i = 0; i < 4; ++i) {
                if ((fl >> i) & 1u) {
                    const float x = px[i], y = py[i];
                    const float pn2 = __fadd_rn(__fmul_rn(x, x), __fmul_rn(y, y));
                    cand[pos++] = make_float4(x, y, pn2, __int_as_float(nbase + i));
                }
            }
        }
        if (tid == 0)                           // sentinel: never wins
            cand[total] = make_float4(0.0f, 0.0f, 3.0e38f, __int_as_float(NPTS));
    }
    __syncthreads();

    // ---- phase B: exact argmin, 2 interleaved accumulators ----
    const int r = r0 + (tid >> 4);
    const int c = c0 + (tid & 15);
    const float gx = ((float)c + 0.5f) * (1.0f / GW);
    const float gy = ((float)r + 0.5f) * (1.0f / GH);

    float bestA = 3.4e38f, bestB = 3.4e38f;
    int   bnA   = NPTS,    bnB   = NPTS;
    int   bn;

    if (!overflow) {
        const int tr = (total + 1) & ~1;        // sentinel pads odd totals
        for (int i = 0; i < tr; i += 2) {
            const float4 qa = cand[i];
            const float4 qb = cand[i + 1];
            const float da = __fmaf_rn(-2.0f, __fmaf_rn(gy, qa.y, __fmul_rn(gx, qa.x)), qa.z);
            const float db = __fmaf_rn(-2.0f, __fmaf_rn(gy, qb.y, __fmul_rn(gx, qb.x)), qb.z);
            if (da < bestA) { bestA = da; bnA = __float_as_int(qa.w); }
            if (db < bestB) { bestB = db; bnB = __float_as_int(qb.w); }
        }
        // merge: smaller d2; on exact tie, smaller index (= earlier position)
        bn = (bestB < bestA || (bestB == bestA && bnB < bnA)) ? bnB : bnA;
    } else {
        float best = 3.4e38f; bn = 0;
        for (int n = 0; n < NPTS; ++n) {        // rare exact fallback
            const float x = __ldg(xp + n);
            const float y = __ldg(yp + n);
            const float pn2 = __fadd_rn(__fmul_rn(x, x), __fmul_rn(y, y));
            const float dot = __fmaf_rn(gy, y, __fmul_rn(gx, x));
            const float d2  = __fmaf_rn(-2.0f, dot, pn2);
            if (d2 < best) { best = d2; bn = n; }
        }
    }

    // ---- gather channels + store ----
    const float* Rb = R + b * (NCH * NPTS);
    const int g = r * GW + c;
#pragma unroll
    for (int ch = 0; ch < NCH; ++ch)
        out[(b * NCH + ch) * (GH * GW) + g] = __ldg(Rb + ch * NPTS + bn);
}

extern "C" void kernel_launch(void* const* d_in, const int* in_sizes, int n_in,
                              void* d_out, int out_size)
{
    const float* R  = (const float*)d_in[0];
    const float* XY = (const float*)d_in[1];
    nn_voronoi_reg_kernel<<<2 * TILES_PER_B, TPB>>>(R, XY, (float*)d_out);
}